// round 16
// baseline (speedup 1.0000x reference)
#include <cuda_runtime.h>
#include <cuda_fp16.h>
#include <mma.h>

#define NMAX 100000
#define FIN  128
#define FOUT 64
#define CAP  64                    // per-node bucket capacity (Poisson(16) tail ~1e-20)
#define OVFCAP (1 << 18)

// ---- scratch (static device globals; no allocations allowed) ----
__device__ int    g_deg[NMAX];                 // degree (RED pass, side stream)
__device__ int    g_cur[NMAX + 1];             // fill cursors; [N] = overflow counter
__device__ float  g_dis[NMAX];
__device__ __align__(128) __half g_zs[(size_t)NMAX * FOUT]; // fp16 dis[r]*z[r] (from gemm)
__device__ float  g_Wc[FIN * FOUT];            // fused weight (tf32-rounded)
__device__ float  g_c[FOUT];                   // fused bias (fp32)
__device__ int    g_list[(size_t)NMAX * CAP];  // bucketed source lists, 25.6 MB
__device__ int    g_ovf[2 * OVFCAP];           // (target, source) overflow pairs

// ---------------------------------------------------------------------------
// Degree count only (RED, no return) — feeds dis before the GEMM epilogue.
__global__ void k_deg(const int* __restrict__ ecol, int E) {
    int i = blockIdx.x * blockDim.x + threadIdx.x;
    if (i < E) atomicAdd(&g_deg[ecol[i]], 1);
}

__global__ void k_dis(int N) {
    int i = blockIdx.x * blockDim.x + threadIdx.x;
    if (i < N) g_dis[i] = rsqrtf((float)(g_deg[i] + 1));   // +1 self-loop
}

// Bucket fill with its own cursor array (runs concurrently with k_deg).
__global__ void k_fill_direct(const int* __restrict__ erow,
                              const int* __restrict__ ecol, int E) {
    int i = blockIdx.x * blockDim.x + threadIdx.x;
    if (i >= E) return;
    int c = ecol[i];
    int r = erow[i];
    int slot = atomicAdd(&g_cur[c], 1);
    if (slot < CAP) {
        g_list[(size_t)c * CAP + slot] = r;
    } else {
        int o = atomicAdd(&g_cur[NMAX], 1);
        if (o < OVFCAP) { g_ovf[2 * o] = c; g_ovf[2 * o + 1] = r; }
    }
}

// ---------------------------------------------------------------------------
// Wc[k][o] = sum_m W_gcn[k][m] * W_fc[o][m]  (stored tf32-rna-rounded)
// c[o]     = b_fc[o] + W_fc @ b_gcn           (full fp32)
__global__ void __launch_bounds__(256) k_fuse_w(const float* __restrict__ Wg,
                                                const float* __restrict__ bg,
                                                const float* __restrict__ Wf,
                                                const float* __restrict__ bf) {
    int w = (blockIdx.x * 256 + threadIdx.x) >> 5;
    int lane = threadIdx.x & 31;
    if (w >= (FIN + 1) * FOUT) return;
    int k = w >> 6;
    int o = w & 63;
    const float* wrow = (k < FIN) ? (Wg + (size_t)k * FIN) : bg;
    float s = 0.f;
    #pragma unroll
    for (int m = lane; m < FIN; m += 32) s += wrow[m] * Wf[(size_t)o * FIN + m];
    #pragma unroll
    for (int d = 16; d; d >>= 1) s += __shfl_xor_sync(0xffffffff, s, d);
    if (lane == 0) {
        if (k < FIN) g_Wc[k * FOUT + o] = nvcuda::wmma::__float_to_tf32(s);
        else         g_c[o] = s + bf[o];
    }
}

// ---------------------------------------------------------------------------
// z = x @ Wc via tf32 mma.sync m16n8k8, cp.async double-buffered x pipeline.
// Epilogue writes zs = fp16(dis[r] * z[r]) directly (k_scale eliminated).
__global__ void __launch_bounds__(256) k_gemm(const float* __restrict__ x, int N) {
    __shared__ __align__(16) float xs[2][128][36];  // raw fp32 x chunks, 36.9 KB
    __shared__ uint2 wf[2][4][8][32];               // B fragments, dbl-buffered, 16 KB

    int t = threadIdx.x;
    int w = t >> 5, lane = t & 31;
    int gid = lane >> 2, tig = lane & 3;
    int row0 = blockIdx.x * 128;

    float acc[8][4];
    #pragma unroll
    for (int i = 0; i < 8; i++)
        #pragma unroll
        for (int j = 0; j < 4; j++) acc[i][j] = 0.f;

    auto load_x_chunk = [&](int buf, int kc) {
        #pragma unroll
        for (int i = 0; i < 4; i++) {
            int idx = t + i * 256;          // 1024 x 16B segments
            int r = idx >> 3, seg = idx & 7;
            int gr = row0 + r;
            const float* src = &x[(size_t)((gr < N) ? gr : row0) * FIN + kc + seg * 4];
            unsigned dst = (unsigned)__cvta_generic_to_shared(&xs[buf][r][seg * 4]);
            asm volatile("cp.async.ca.shared.global [%0], [%1], 16;"
                         :: "r"(dst), "l"(src));
        }
        asm volatile("cp.async.commit_group;");
    };
    auto load_wf_chunk = [&](int buf, int kc) {
        #pragma unroll
        for (int i = 0; i < 4; i++) {
            int idx = t + i * 256;
            int ks = idx >> 8, nt = (idx >> 5) & 7, ln = idx & 31;
            int g = ln >> 2, tg = ln & 3;
            uint2 bb;
            bb.x = __float_as_uint(g_Wc[(kc + ks * 8 + tg) * FOUT + nt * 8 + g]);
            bb.y = __float_as_uint(g_Wc[(kc + ks * 8 + tg + 4) * FOUT + nt * 8 + g]);
            wf[buf][ks][nt][ln] = bb;
        }
    };

    load_x_chunk(0, 0);
    load_wf_chunk(0, 0);

    #pragma unroll
    for (int c = 0; c < 4; c++) {
        int cur = c & 1, nxt = cur ^ 1;
        if (c < 3) {
            load_x_chunk(nxt, (c + 1) * 32);
            load_wf_chunk(nxt, (c + 1) * 32);
            asm volatile("cp.async.wait_group 1;");
        } else {
            asm volatile("cp.async.wait_group 0;");
        }
        __syncthreads();

        #pragma unroll
        for (int ks = 0; ks < 4; ks++) {
            int r = w * 16 + gid;
            unsigned a0 = __float_as_uint(nvcuda::wmma::__float_to_tf32(xs[cur][r][ks * 8 + tig]));
            unsigned a1 = __float_as_uint(nvcuda::wmma::__float_to_tf32(xs[cur][r + 8][ks * 8 + tig]));
            unsigned a2 = __float_as_uint(nvcuda::wmma::__float_to_tf32(xs[cur][r][ks * 8 + tig + 4]));
            unsigned a3 = __float_as_uint(nvcuda::wmma::__float_to_tf32(xs[cur][r + 8][ks * 8 + tig + 4]));
            #pragma unroll
            for (int nt = 0; nt < 8; nt++) {
                uint2 b = wf[cur][ks][nt][lane];
                asm volatile(
                    "mma.sync.aligned.m16n8k8.row.col.f32.tf32.tf32.f32 "
                    "{%0,%1,%2,%3}, {%4,%5,%6,%7}, {%8,%9}, {%0,%1,%2,%3};"
                    : "+f"(acc[nt][0]), "+f"(acc[nt][1]),
                      "+f"(acc[nt][2]), "+f"(acc[nt][3])
                    : "r"(a0), "r"(a1), "r"(a2), "r"(a3), "r"(b.x), "r"(b.y));
            }
        }
        __syncthreads();
    }

    // epilogue: zs = fp16(dis[r] * z[r])  (single fp16 rounding)
    int rbase = row0 + w * 16 + gid;
    #pragma unroll
    for (int half = 0; half < 2; half++) {
        int r = rbase + half * 8;
        if (r < N) {
            float d = g_dis[r];
            #pragma unroll
            for (int nt = 0; nt < 8; nt++) {
                int col = nt * 8 + tig * 2;
                __half2 h = __float22half2_rn(
                    make_float2(d * acc[nt][half * 2 + 0], d * acc[nt][half * 2 + 1]));
                *(unsigned*)&g_zs[(size_t)r * FOUT + col] = *(unsigned*)&h;
            }
        }
    }
}

// ---------------------------------------------------------------------------
// Aggregation incl. self-loop + inline overflow:
//   out[c] = cb + dis[c] * (zs[c] + sum_r zs[r])   (zs pre-scaled by dis[r])
__global__ void __launch_bounds__(256) k_aggr(float* __restrict__ out, int N) {
    int w = (blockIdx.x * 256 + threadIdx.x) >> 5;
    int lane = threadIdx.x & 31;
    if (w >= N) return;
    int c = w;
    int degRaw = g_cur[c];
    int deg = min(degRaw, CAP);
    const int* lst = &g_list[(size_t)c * CAP];

    unsigned us = *(const unsigned*)&g_zs[(size_t)c * FOUT + lane * 2];
    float2 acc = __half22float2(*reinterpret_cast<__half2*>(&us));

    for (int base = 0; base < deg; base += 32) {
        int cnt = min(32, deg - base);
        int rl = (lane < cnt) ? __ldg(&lst[base + lane]) : 0;
        int j = 0;
        for (; j + 4 <= cnt; j += 4) {
            int r0 = __shfl_sync(0xffffffff, rl, j);
            int r1 = __shfl_sync(0xffffffff, rl, j + 1);
            int r2 = __shfl_sync(0xffffffff, rl, j + 2);
            int r3 = __shfl_sync(0xffffffff, rl, j + 3);
            unsigned u0 = *(const unsigned*)&g_zs[(size_t)r0 * FOUT + lane * 2];
            unsigned u1 = *(const unsigned*)&g_zs[(size_t)r1 * FOUT + lane * 2];
            unsigned u2 = *(const unsigned*)&g_zs[(size_t)r2 * FOUT + lane * 2];
            unsigned u3 = *(const unsigned*)&g_zs[(size_t)r3 * FOUT + lane * 2];
            float2 f0 = __half22float2(*reinterpret_cast<__half2*>(&u0));
            float2 f1 = __half22float2(*reinterpret_cast<__half2*>(&u1));
            float2 f2 = __half22float2(*reinterpret_cast<__half2*>(&u2));
            float2 f3 = __half22float2(*reinterpret_cast<__half2*>(&u3));
            acc.x += f0.x + f1.x + f2.x + f3.x;
            acc.y += f0.y + f1.y + f2.y + f3.y;
        }
        for (; j < cnt; j++) {
            int r = __shfl_sync(0xffffffff, rl, j);
            unsigned u = *(const unsigned*)&g_zs[(size_t)r * FOUT + lane * 2];
            float2 f = __half22float2(*reinterpret_cast<__half2*>(&u));
            acc.x += f.x; acc.y += f.y;
        }
    }

    if (degRaw > CAP) {                       // inline overflow (fires ~never)
        int cnt = min(g_cur[NMAX], OVFCAP);
        for (int e = 0; e < cnt; e++) {
            if (g_ovf[2 * e] == c) {
                int r = g_ovf[2 * e + 1];
                unsigned u = *(const unsigned*)&g_zs[(size_t)r * FOUT + lane * 2];
                float2 f = __half22float2(*reinterpret_cast<__half2*>(&u));
                acc.x += f.x; acc.y += f.y;
            }
        }
    }

    float dc = g_dis[c];
    float2 cb = *(const float2*)&g_c[lane * 2];
    float2 ov;
    ov.x = cb.x + dc * acc.x;
    ov.y = cb.y + dc * acc.y;
    *(float2*)&out[(size_t)c * FOUT + lane * 2] = ov;
}

// ---------------------------------------------------------------------------
// 1 extra stream + 2 events (proven-safe resource profile):
//   s2:      memset(deg) -> fuse_w -> k_deg -> k_dis -> gemm(writes dis*z) [eGemm]
//   stream0: memset(cur) -> fill_direct -> [wait eGemm] -> aggr
extern "C" void kernel_launch(void* const* d_in, const int* in_sizes, int n_in,
                              void* d_out, int out_size) {
    const float* x  = (const float*)d_in[0];
    const int*   ei = (const int*)d_in[1];
    const float* Wg = (const float*)d_in[2];
    const float* bg = (const float*)d_in[3];
    const float* Wf = (const float*)d_in[4];
    const float* bf = (const float*)d_in[5];
    float* out = (float*)d_out;

    int N = in_sizes[0] / FIN;
    int E = in_sizes[1] / 2;
    const int* erow = ei;        // sources
    const int* ecol = ei + E;    // targets (aggregation index)

    cudaStream_t s2;
    cudaStreamCreateWithFlags(&s2, cudaStreamNonBlocking);
    cudaEvent_t eFork, eGemm;
    cudaEventCreateWithFlags(&eFork, cudaEventDisableTiming);
    cudaEventCreateWithFlags(&eGemm, cudaEventDisableTiming);

    void* degPtr = nullptr; void* curPtr = nullptr;
    cudaGetSymbolAddress(&degPtr, g_deg);
    cudaGetSymbolAddress(&curPtr, g_cur);

    cudaEventRecord(eFork, 0);
    cudaStreamWaitEvent(s2, eFork, 0);

    // s2: degree -> dis -> weights -> gemm (epilogue applies dis)
    cudaMemsetAsync(degPtr, 0, (size_t)NMAX * sizeof(int), s2);
    k_fuse_w<<<((FIN + 1) * FOUT * 32 + 255) / 256, 256, 0, s2>>>(Wg, bg, Wf, bf);
    k_deg<<<(E + 255) / 256, 256, 0, s2>>>(ecol, E);
    k_dis<<<(N + 255) / 256, 256, 0, s2>>>(N);
    k_gemm<<<(N + 127) / 128, 256, 0, s2>>>(x, N);
    cudaEventRecord(eGemm, s2);

    // main: bucket fill (own cursors), then aggregate at the join
    cudaMemsetAsync(curPtr, 0, (size_t)(NMAX + 1) * sizeof(int), 0);
    k_fill_direct<<<(E + 255) / 256, 256>>>(erow, ecol, E);
    cudaStreamWaitEvent(0, eGemm, 0);
    k_aggr<<<(N * 32 + 255) / 256, 256>>>(out, N);
}

// round 17
// speedup vs baseline: 1.1407x; 1.1407x over previous
#include <cuda_runtime.h>
#include <cuda_fp16.h>
#include <mma.h>

#define NMAX 100000
#define FIN  128
#define FOUT 64
#define CAP  64                    // per-node bucket capacity (Poisson(16) tail ~1e-20)
#define OVFCAP (1 << 18)

// ---- scratch (static device globals; no allocations allowed) ----
__device__ int    g_deg[NMAX + 1];             // [N] = overflow counter (one memset)
__device__ float  g_dis[NMAX];
__device__ __align__(128) __half g_zs[(size_t)NMAX * FOUT]; // fp16 z; dis*z after k_scale
__device__ float  g_Wc[FIN * FOUT];            // fused weight (tf32-rounded)
__device__ float  g_c[FOUT];                   // fused bias (fp32)
__device__ int    g_list[(size_t)NMAX * CAP];  // bucketed source lists, 25.6 MB
__device__ int    g_ovf[2 * OVFCAP];           // (target, source) overflow pairs

// ---------------------------------------------------------------------------
// Single-pass bucket fill: counts degree AND records sources.
__global__ void k_fill_direct(const int* __restrict__ erow,
                              const int* __restrict__ ecol, int E) {
    int i = blockIdx.x * blockDim.x + threadIdx.x;
    if (i >= E) return;
    int c = ecol[i];
    int r = erow[i];
    int slot = atomicAdd(&g_deg[c], 1);
    if (slot < CAP) {
        g_list[(size_t)c * CAP + slot] = r;
    } else {
        int o = atomicAdd(&g_deg[NMAX], 1);
        if (o < OVFCAP) { g_ovf[2 * o] = c; g_ovf[2 * o + 1] = r; }
    }
}

// ---------------------------------------------------------------------------
// Wc[k][o] = sum_m W_gcn[k][m] * W_fc[o][m]  (stored tf32-rna-rounded)
// c[o]     = b_fc[o] + W_fc @ b_gcn           (full fp32)
__global__ void __launch_bounds__(256) k_fuse_w(const float* __restrict__ Wg,
                                                const float* __restrict__ bg,
                                                const float* __restrict__ Wf,
                                                const float* __restrict__ bf) {
    int w = (blockIdx.x * 256 + threadIdx.x) >> 5;
    int lane = threadIdx.x & 31;
    if (w >= (FIN + 1) * FOUT) return;
    int k = w >> 6;
    int o = w & 63;
    const float* wrow = (k < FIN) ? (Wg + (size_t)k * FIN) : bg;
    float s = 0.f;
    #pragma unroll
    for (int m = lane; m < FIN; m += 32) s += wrow[m] * Wf[(size_t)o * FIN + m];
    #pragma unroll
    for (int d = 16; d; d >>= 1) s += __shfl_xor_sync(0xffffffff, s, d);
    if (lane == 0) {
        if (k < FIN) g_Wc[k * FOUT + o] = nvcuda::wmma::__float_to_tf32(s);
        else         g_c[o] = s + bf[o];
    }
}

// ---------------------------------------------------------------------------
// z = x @ Wc via tf32 mma.sync m16n8k8.
// cp.async double-buffers RAW fp32 x only (36.9 KB); wf single-buffered (8 KB)
// -> 45 KB smem, 3 CTAs/SM. rna conversion at A-fragment load. RAW fp16 z out.
__global__ void __launch_bounds__(256) k_gemm(const float* __restrict__ x, int N) {
    __shared__ __align__(16) float xs[2][128][36];  // raw fp32 x chunks
    __shared__ uint2 wf[4][8][32];                  // B fragments (per-chunk rebuild)

    int t = threadIdx.x;
    int w = t >> 5, lane = t & 31;
    int gid = lane >> 2, tig = lane & 3;
    int row0 = blockIdx.x * 128;

    float acc[8][4];
    #pragma unroll
    for (int i = 0; i < 8; i++)
        #pragma unroll
        for (int j = 0; j < 4; j++) acc[i][j] = 0.f;

    auto load_x_chunk = [&](int buf, int kc) {
        #pragma unroll
        for (int i = 0; i < 4; i++) {
            int idx = t + i * 256;          // 1024 x 16B segments
            int r = idx >> 3, seg = idx & 7;
            int gr = row0 + r;
            const float* src = &x[(size_t)((gr < N) ? gr : row0) * FIN + kc + seg * 4];
            unsigned dst = (unsigned)__cvta_generic_to_shared(&xs[buf][r][seg * 4]);
            asm volatile("cp.async.ca.shared.global [%0], [%1], 16;"
                         :: "r"(dst), "l"(src));
        }
        asm volatile("cp.async.commit_group;");
    };
    auto load_wf_chunk = [&](int kc) {
        #pragma unroll
        for (int i = 0; i < 4; i++) {
            int idx = t + i * 256;
            int ks = idx >> 8, nt = (idx >> 5) & 7, ln = idx & 31;
            int g = ln >> 2, tg = ln & 3;
            uint2 bb;
            bb.x = __float_as_uint(g_Wc[(kc + ks * 8 + tg) * FOUT + nt * 8 + g]);
            bb.y = __float_as_uint(g_Wc[(kc + ks * 8 + tg + 4) * FOUT + nt * 8 + g]);
            wf[ks][nt][ln] = bb;
        }
    };

    load_x_chunk(0, 0);   // chunk 0 in flight

    #pragma unroll
    for (int c = 0; c < 4; c++) {
        int cur = c & 1, nxt = cur ^ 1;
        load_wf_chunk(c * 32);            // safe: barrier at end of prev iter
        if (c < 3) {
            load_x_chunk(nxt, (c + 1) * 32);   // nxt buf free since prev-iter barrier
            asm volatile("cp.async.wait_group 1;");   // chunk c resident
        } else {
            asm volatile("cp.async.wait_group 0;");
        }
        __syncthreads();

        #pragma unroll
        for (int ks = 0; ks < 4; ks++) {
            int r = w * 16 + gid;
            unsigned a0 = __float_as_uint(nvcuda::wmma::__float_to_tf32(xs[cur][r][ks * 8 + tig]));
            unsigned a1 = __float_as_uint(nvcuda::wmma::__float_to_tf32(xs[cur][r + 8][ks * 8 + tig]));
            unsigned a2 = __float_as_uint(nvcuda::wmma::__float_to_tf32(xs[cur][r][ks * 8 + tig + 4]));
            unsigned a3 = __float_as_uint(nvcuda::wmma::__float_to_tf32(xs[cur][r + 8][ks * 8 + tig + 4]));
            #pragma unroll
            for (int nt = 0; nt < 8; nt++) {
                uint2 b = wf[ks][nt][lane];
                asm volatile(
                    "mma.sync.aligned.m16n8k8.row.col.f32.tf32.tf32.f32 "
                    "{%0,%1,%2,%3}, {%4,%5,%6,%7}, {%8,%9}, {%0,%1,%2,%3};"
                    : "+f"(acc[nt][0]), "+f"(acc[nt][1]),
                      "+f"(acc[nt][2]), "+f"(acc[nt][3])
                    : "r"(a0), "r"(a1), "r"(a2), "r"(a3), "r"(b.x), "r"(b.y));
            }
        }
        __syncthreads();
    }

    // epilogue: raw fp16 z (k_scale applies dis afterwards — r14 numerics)
    int rbase = row0 + w * 16 + gid;
    #pragma unroll
    for (int half = 0; half < 2; half++) {
        int r = rbase + half * 8;
        if (r < N) {
            #pragma unroll
            for (int nt = 0; nt < 8; nt++) {
                int col = nt * 8 + tig * 2;
                __half2 h = __float22half2_rn(
                    make_float2(acc[nt][half * 2 + 0], acc[nt][half * 2 + 1]));
                *(unsigned*)&g_zs[(size_t)r * FOUT + col] = *(unsigned*)&h;
            }
        }
    }
}

// ---------------------------------------------------------------------------
// dis[r] = rsqrt(deg[r]+1); zs[r] *= dis[r].  (r14 version, at its BW floor)
__global__ void __launch_bounds__(256) k_scale(int N) {
    int gid = blockIdx.x * 256 + threadIdx.x;
    int row = gid >> 2;
    if (row >= N) return;
    float d = rsqrtf((float)(g_deg[row] + 1));   // +1 self-loop
    if ((gid & 3) == 0) g_dis[row] = d;
    uint4* p = (uint4*)&g_zs[(size_t)row * FOUT + (gid & 3) * 16];
    uint4 u0 = p[0], u1 = p[1];
    unsigned* a = (unsigned*)&u0;
    unsigned* b = (unsigned*)&u1;
    #pragma unroll
    for (int i = 0; i < 4; i++) {
        float2 f0 = __half22float2(*reinterpret_cast<__half2*>(&a[i]));
        float2 f1 = __half22float2(*reinterpret_cast<__half2*>(&b[i]));
        __half2 h0 = __float22half2_rn(make_float2(d * f0.x, d * f0.y));
        __half2 h1 = __float22half2_rn(make_float2(d * f1.x, d * f1.y));
        a[i] = *(unsigned*)&h0;
        b[i] = *(unsigned*)&h1;
    }
    p[0] = u0; p[1] = u1;
}

// ---------------------------------------------------------------------------
// Aggregation incl. self-loop + inline overflow:
//   out[c] = cb + dis[c] * (zs[c] + sum_r zs[r])   (zs pre-scaled by dis[r])
__global__ void __launch_bounds__(256) k_aggr(float* __restrict__ out, int N) {
    int w = (blockIdx.x * 256 + threadIdx.x) >> 5;
    int lane = threadIdx.x & 31;
    if (w >= N) return;
    int c = w;
    int degRaw = g_deg[c];
    int deg = min(degRaw, CAP);
    const int* lst = &g_list[(size_t)c * CAP];

    unsigned us = *(const unsigned*)&g_zs[(size_t)c * FOUT + lane * 2];
    float2 acc = __half22float2(*reinterpret_cast<__half2*>(&us));

    for (int base = 0; base < deg; base += 32) {
        int cnt = min(32, deg - base);
        int rl = (lane < cnt) ? __ldg(&lst[base + lane]) : 0;
        int j = 0;
        for (; j + 4 <= cnt; j += 4) {
            int r0 = __shfl_sync(0xffffffff, rl, j);
            int r1 = __shfl_sync(0xffffffff, rl, j + 1);
            int r2 = __shfl_sync(0xffffffff, rl, j + 2);
            int r3 = __shfl_sync(0xffffffff, rl, j + 3);
            unsigned u0 = *(const unsigned*)&g_zs[(size_t)r0 * FOUT + lane * 2];
            unsigned u1 = *(const unsigned*)&g_zs[(size_t)r1 * FOUT + lane * 2];
            unsigned u2 = *(const unsigned*)&g_zs[(size_t)r2 * FOUT + lane * 2];
            unsigned u3 = *(const unsigned*)&g_zs[(size_t)r3 * FOUT + lane * 2];
            float2 f0 = __half22float2(*reinterpret_cast<__half2*>(&u0));
            float2 f1 = __half22float2(*reinterpret_cast<__half2*>(&u1));
            float2 f2 = __half22float2(*reinterpret_cast<__half2*>(&u2));
            float2 f3 = __half22float2(*reinterpret_cast<__half2*>(&u3));
            acc.x += f0.x + f1.x + f2.x + f3.x;
            acc.y += f0.y + f1.y + f2.y + f3.y;
        }
        for (; j < cnt; j++) {
            int r = __shfl_sync(0xffffffff, rl, j);
            unsigned u = *(const unsigned*)&g_zs[(size_t)r * FOUT + lane * 2];
            float2 f = __half22float2(*reinterpret_cast<__half2*>(&u));
            acc.x += f.x; acc.y += f.y;
        }
    }

    if (degRaw > CAP) {                       // inline overflow (fires ~never)
        int cnt = min(g_deg[NMAX], OVFCAP);
        for (int e = 0; e < cnt; e++) {
            if (g_ovf[2 * e] == c) {
                int r = g_ovf[2 * e + 1];
                unsigned u = *(const unsigned*)&g_zs[(size_t)r * FOUT + lane * 2];
                float2 f = __half22float2(*reinterpret_cast<__half2*>(&u));
                acc.x += f.x; acc.y += f.y;
            }
        }
    }

    float dc = g_dis[c];
    float2 cb = *(const float2*)&g_c[lane * 2];
    float2 ov;
    ov.x = cb.x + dc * acc.x;
    ov.y = cb.y + dc * acc.y;
    *(float2*)&out[(size_t)c * FOUT + lane * 2] = ov;
}

// ---------------------------------------------------------------------------
// r14 schedule (proven): 1 extra stream + 2 events.
//   s2:      fuse_w -> gemm [eGemm]
//   stream0: memset(deg+ovf) -> fill_direct -> [wait eGemm] -> scale -> aggr
extern "C" void kernel_launch(void* const* d_in, const int* in_sizes, int n_in,
                              void* d_out, int out_size) {
    const float* x  = (const float*)d_in[0];
    const int*   ei = (const int*)d_in[1];
    const float* Wg = (const float*)d_in[2];
    const float* bg = (const float*)d_in[3];
    const float* Wf = (const float*)d_in[4];
    const float* bf = (const float*)d_in[5];
    float* out = (float*)d_out;

    int N = in_sizes[0] / FIN;
    int E = in_sizes[1] / 2;
    const int* erow = ei;        // sources
    const int* ecol = ei + E;    // targets (aggregation index)

    cudaStream_t s2;
    cudaStreamCreateWithFlags(&s2, cudaStreamNonBlocking);
    cudaEvent_t eFork, eGemm;
    cudaEventCreateWithFlags(&eFork, cudaEventDisableTiming);
    cudaEventCreateWithFlags(&eGemm, cudaEventDisableTiming);

    void* degPtr = nullptr;
    cudaGetSymbolAddress(&degPtr, g_deg);

    // fork: dense pipeline on side stream
    cudaEventRecord(eFork, 0);
    cudaStreamWaitEvent(s2, eFork, 0);
    k_fuse_w<<<((FIN + 1) * FOUT * 32 + 255) / 256, 256, 0, s2>>>(Wg, bg, Wf, bf);
    k_gemm<<<(N + 127) / 128, 256, 0, s2>>>(x, N);
    cudaEventRecord(eGemm, s2);

    // main branch: one memset (deg + overflow counter), bucket fill
    cudaMemsetAsync(degPtr, 0, (size_t)(NMAX + 1) * sizeof(int), 0);
    k_fill_direct<<<(E + 255) / 256, 256>>>(erow, ecol, E);

    // join: scale (needs gemm + final deg), then aggregate (with inline ovf)
    cudaStreamWaitEvent(0, eGemm, 0);
    k_scale<<<(N * 4 + 255) / 256, 256>>>(N);
    k_aggr<<<(N * 32 + 255) / 256, 256>>>(out, N);
}